// round 12
// baseline (speedup 1.0000x reference)
#include <cuda_runtime.h>
#include <cstdint>

#define V 8192
#define NB 64
#define M3 24576
#define STRIDE 8194
#define MT 128
#define NTILE 192            // 24576 / 128 m-tiles
#define KS 32                // split-K factor -> 256 K per unit
#define UNITK 256
#define NUNITS (NTILE * KS)  // 6144
#define GRID 296             // persistent, 2 CTAs/SM

#define PFW 72               // f tile pitch (words): 8q+qid banks, conflict-free
#define PD 72

#define FROWS 128            // k2 rows per unit (256 k / 2)
#define FBUF_WORDS (FROWS * PFW)             // 9216
#define FBUF_BYTES (FBUF_WORDS * 4)          // 36864
#define DS_OFF    (2 * FBUF_WORDS)           // 18432 words
#define SOUT_OFF  (DS_OFF + 64 * PD)         // 23040
#define SMEM_DYN  ((SOUT_OFF + 192) * 4)     // 92928 B -> 2 CTAs/SM

#define MMA_BF16(d, a0, a1, a2, a3, b0, b1)                                   \
    asm volatile("mma.sync.aligned.m16n8k16.row.col.f32.bf16.bf16.f32 "       \
        "{%0,%1,%2,%3}, {%4,%5,%6,%7}, {%8,%9}, {%0,%1,%2,%3};"               \
        : "+f"((d)[0]), "+f"((d)[1]), "+f"((d)[2]), "+f"((d)[3])              \
        : "r"(a0), "r"(a1), "r"(a2), "r"(a3), "r"(b0), "r"(b1))

#define CP16(dst_u32, src_gl) \
    asm volatile("cp.async.cg.shared.global [%0], [%1], 16;" :: "r"(dst_u32), "l"(src_gl))
#define CP_COMMIT()  asm volatile("cp.async.commit_group;" ::: "memory")
#define CP_WAIT0()   asm volatile("cp.async.wait_group 0;" ::: "memory")

// f packed as bf16 k-pairs: g_fP[i2*64 + b] = {lo: f[b][2*i2], hi: f[b][2*i2+1]}
__device__ unsigned g_fP[(V / 2) * NB];   // 1 MB, L2-resident

__device__ __forceinline__ unsigned pack_bf16(float lo, float hi) {
    unsigned r;
    asm("cvt.rn.bf16x2.f32 %0, %1, %2;" : "=r"(r) : "f"(hi), "f"(lo));
    return r;
}

// ---------------------------------------------------------------------------
__global__ void prep_kernel(const float* __restrict__ func, float* __restrict__ out) {
    int idx = blockIdx.x * 256 + threadIdx.x;    // < (V/2)*NB = 262144
    int i2 = idx >> 6;
    int b  = idx & 63;
    float lo = func[b * STRIDE + 2 * i2];
    float hi = func[b * STRIDE + 2 * i2 + 1];
    g_fP[idx] = pack_bf16(lo, hi);
    if (idx < NB) {
        const float QI = 1000000000.0f;
        float a1 = func[idx * STRIDE + V];
        float a2 = func[idx * STRIDE + V + 1];
        out[idx * 3 + 0] = a1 * -QI;
        out[idx * 3 + 1] = (1.0f - (1.0f - a1) * (1.0f - a2)) * -QI;
        out[idx * 3 + 2] = 0.0f;
    }
}

// ---------------------------------------------------------------------------
// Persistent bf16 mma.sync GEMM: C direct-LDG (no staging), f in SMEM.
// Units = 128m x 256K; barriers only at unit boundaries.
// ---------------------------------------------------------------------------
__global__ __launch_bounds__(256, 2)
void cooc_mma(const float* __restrict__ cooc,
              const float* __restrict__ arg,
              float* __restrict__ out) {
    extern __shared__ float sm[];
    float* Ds   = sm + DS_OFF;
    float* sout = sm + SOUT_OFF;

    const int tid  = threadIdx.x;
    const int lane = tid & 31;
    const int wid  = tid >> 5;
    const int mg   = wid & 3;          // m-group: 32 m each
    const int kg   = wid >> 2;         // k16-group within 32-k block
    const int quad = lane & 3;
    const int qid  = lane >> 2;
    const int bid  = blockIdx.x;

    const int nu = 1 + (NUNITS - 1 - bid) / GRID;

    unsigned smem_base;
    asm("{ .reg .u64 t; cvta.to.shared.u64 t, %1; cvt.u32.u64 %0, t; }"
        : "=r"(smem_base) : "l"(sm));

    const char* fP_g = (const char*)__cvta_generic_to_global(g_fP);

    // f copy slots: 512 16B-chunks, 2 per thread
    const int fc0_row = tid >> 2,         fc0_c16 = tid & 3;
    const int fc1_row = (tid + 256) >> 2, fc1_c16 = tid & 3;

    auto issue_f = [&](int k0n, int bufn) {
        unsigned dst = smem_base + (unsigned)bufn * FBUF_BYTES;
        const char* src = fP_g + ((size_t)((k0n >> 1) + fc0_row) * 64 + fc0_c16 * 4) * 4;
        CP16(dst + (unsigned)(fc0_row * PFW + fc0_c16 * 4) * 4, src);
        const char* src1 = fP_g + ((size_t)((k0n >> 1) + fc1_row) * 64 + fc1_c16 * 4) * 4;
        CP16(dst + (unsigned)(fc1_row * PFW + fc1_c16 * 4) * 4, src1);
    };

    float acc[2][8][4];
    #pragma unroll
    for (int mt = 0; mt < 2; mt++)
        #pragma unroll
        for (int nt = 0; nt < 8; nt++)
            #pragma unroll
            for (int r = 0; r < 4; r++) acc[mt][nt][r] = 0.0f;

    float po0 = 0.f, po1 = 0.f, po2 = 0.f;
    const int bb = tid & 63;
    const int mq = tid >> 6;
    const float* argb = arg + bb * STRIDE;

    // unit 0 state
    int u_c = bid;
    int m0_c, k0_c;
    {
        int ks = u_c / NTILE;
        m0_c = (u_c - ks * NTILE) * MT;
        k0_c = ks * UNITK;
    }
    const float* cbase = cooc + (size_t)(k0_c + kg * 16 + 2 * quad) * M3
                              + m0_c + mg * 32 + qid;

    // prologue: f(0) + C prefetch(j=0)
    issue_f(k0_c, 0);
    CP_COMMIT();

    float cpre[16];
    #pragma unroll
    for (int r = 0; r < 4; r++) {
        int ro = (r & 1) + ((r >> 1) << 3);          // 0,1,8,9
        #pragma unroll
        for (int c = 0; c < 4; c++)
            cpre[r * 4 + c] = __ldg(cbase + (size_t)ro * M3 + c * 8);
    }

    CP_WAIT0();
    __syncthreads();

    for (int ui = 0; ui < nu; ui++) {
        // next-unit state
        int u_n = u_c + GRID;
        int m0_n = m0_c, k0_n = k0_c;
        const float* cbase_next = cbase;
        if (u_n < NUNITS) {
            int ks = u_n / NTILE;
            m0_n = (u_n - ks * NTILE) * MT;
            k0_n = ks * UNITK;
            cbase_next = cooc + (size_t)(k0_n + kg * 16 + 2 * quad) * M3
                              + m0_n + mg * 32 + qid;
        }
        if (ui + 1 < nu) { issue_f(k0_n, (ui + 1) & 1); }
        CP_COMMIT();

        const unsigned* fwords = (const unsigned*)sm + (ui & 1) * FBUF_WORDS;

        #pragma unroll
        for (int j = 0; j < 8; j++) {
            // pack A-fragments from prefetched C
            unsigned apk[2][4];
            #pragma unroll
            for (int mt = 0; mt < 2; mt++) {
                int c0 = 2 * mt, c1 = 2 * mt + 1;
                apk[mt][0] = pack_bf16(cpre[0 + c0], cpre[4 + c0]);   // k, k+1
                apk[mt][1] = pack_bf16(cpre[0 + c1], cpre[4 + c1]);
                apk[mt][2] = pack_bf16(cpre[8 + c0], cpre[12 + c0]);  // k+8, k+9
                apk[mt][3] = pack_bf16(cpre[8 + c1], cpre[12 + c1]);
            }

            // prefetch next k16 step (or next unit's j=0)
            const float* np = (j < 7) ? cbase + (size_t)(j + 1) * 32 * M3 : cbase_next;
            #pragma unroll
            for (int r = 0; r < 4; r++) {
                int ro = (r & 1) + ((r >> 1) << 3);
                #pragma unroll
                for (int c = 0; c < 4; c++)
                    cpre[r * 4 + c] = __ldg(np + (size_t)ro * M3 + c * 8);
            }

            // B-fragments from f SMEM
            const unsigned* fb = fwords + (kg * 8 + 16 * j + quad) * PFW + qid;
            unsigned b0[8], b1[8];
            #pragma unroll
            for (int nt = 0; nt < 8; nt++) {
                b0[nt] = fb[nt * 8];
                b1[nt] = fb[4 * PFW + nt * 8];
            }

            #pragma unroll
            for (int mt = 0; mt < 2; mt++)
                #pragma unroll
                for (int nt = 0; nt < 8; nt++)
                    MMA_BF16(acc[mt][nt], apk[mt][0], apk[mt][1], apk[mt][2], apk[mt][3],
                             b0[nt], b1[nt]);
        }

        // ---- unit epilogue: two-pass fold + arg-weighted reduce ----
        #pragma unroll
        for (int p = 0; p < 2; p++) {
            __syncthreads();
            if (kg == 0) {
                int cr = mg * 16 + qid;
                #pragma unroll
                for (int nt = 0; nt < 8; nt++) {
                    int bc = nt * 8 + 2 * quad;
                    Ds[cr * PD + bc]           = acc[p][nt][0];
                    Ds[cr * PD + bc + 1]       = acc[p][nt][1];
                    Ds[(cr + 8) * PD + bc]     = acc[p][nt][2];
                    Ds[(cr + 8) * PD + bc + 1] = acc[p][nt][3];
                }
            }
            __syncthreads();
            if (kg == 1) {
                int cr = mg * 16 + qid;
                #pragma unroll
                for (int nt = 0; nt < 8; nt++) {
                    int bc = nt * 8 + 2 * quad;
                    Ds[cr * PD + bc]           += acc[p][nt][0];
                    Ds[cr * PD + bc + 1]       += acc[p][nt][1];
                    Ds[(cr + 8) * PD + bc]     += acc[p][nt][2];
                    Ds[(cr + 8) * PD + bc + 1] += acc[p][nt][3];
                }
            }
            __syncthreads();
            #pragma unroll 4
            for (int mm = 0; mm < 16; mm++) {
                int m = m0_c + mq * 32 + p * 16 + mm;
                unsigned j3 = (unsigned)m / 3u;
                int k = m - 3 * (int)j3;
                float t = Ds[(mq * 16 + mm) * PD + bb] * __ldg(argb + j3);
                if (k == 0) po0 += t;
                else if (k == 1) po1 += t;
                else po2 += t;
            }
        }

        #pragma unroll
        for (int mt = 0; mt < 2; mt++)
            #pragma unroll
            for (int nt = 0; nt < 8; nt++)
                #pragma unroll
                for (int r = 0; r < 4; r++) acc[mt][nt][r] = 0.0f;

        // advance, wait f(ui+1)
        u_c = u_n; m0_c = m0_n; k0_c = k0_n; cbase = cbase_next;
        CP_WAIT0();
        __syncthreads();
    }

    // ---- final flush ----
    if (tid < 192) sout[tid] = 0.0f;
    __syncthreads();
    atomicAdd(&sout[bb * 3 + 0], po0);
    atomicAdd(&sout[bb * 3 + 1], po1);
    atomicAdd(&sout[bb * 3 + 2], po2);
    __syncthreads();
    if (tid < 192) atomicAdd(&out[tid], sout[tid]);
}

// ---------------------------------------------------------------------------
extern "C" void kernel_launch(void* const* d_in, const int* in_sizes, int n_in,
                              void* d_out, int out_size) {
    const float* func = (const float*)d_in[0];
    const float* arg  = (const float*)d_in[1];
    const float* cooc = (const float*)d_in[2];
    float* out = (float*)d_out;

    cudaFuncSetAttribute(cooc_mma, cudaFuncAttributeMaxDynamicSharedMemorySize, SMEM_DYN);

    prep_kernel<<<((V / 2) * NB) / 256, 256>>>(func, out);
    cooc_mma<<<GRID, 256, SMEM_DYN>>>(cooc, arg, out);
}

// round 13
// speedup vs baseline: 1.0325x; 1.0325x over previous
#include <cuda_runtime.h>
#include <cstdint>

#define V 8192
#define NB 64
#define M3 24576
#define STRIDE 8194
#define MT 64
#define NTILE 384            // 24576 / 64 m-tiles
#define KS 16                // split-K -> 512 K per unit
#define NUNITS (NTILE * KS)  // 6144
#define GRID 592             // persistent, 4 CTAs/SM
#define KC 32
#define SPU 16               // stages per unit
#define NST 3                // cp.async ring depth

#define PC 68                // C tile pitch: 2-row stride 136%32=8 -> conflict-free
#define PFW 72               // f pair-tile pitch (words)
#define PD 72

#define CS_FLOATS (KC * PC)                  // 2176
#define FS_WORDS  (16 * PFW)                 // 1152
#define SB_FLOATS (CS_FLOATS + FS_WORDS)     // 3328
#define SB_BYTES  (SB_FLOATS * 4)            // 13312
#define DS_OFF    (NST * SB_FLOATS)          // 9984
#define SOUT_OFF  (DS_OFF + 32 * PD)         // 12288
#define SMEM_DYN  ((SOUT_OFF + 192) * 4)     // 49920 B -> 4 CTAs/SM

#define MMA_BF16(d, a0, a1, a2, a3, b0, b1)                                   \
    asm volatile("mma.sync.aligned.m16n8k16.row.col.f32.bf16.bf16.f32 "       \
        "{%0,%1,%2,%3}, {%4,%5,%6,%7}, {%8,%9}, {%0,%1,%2,%3};"               \
        : "+f"((d)[0]), "+f"((d)[1]), "+f"((d)[2]), "+f"((d)[3])              \
        : "r"(a0), "r"(a1), "r"(a2), "r"(a3), "r"(b0), "r"(b1))

#define CP16(dst_u32, src_gl) \
    asm volatile("cp.async.cg.shared.global [%0], [%1], 16;" :: "r"(dst_u32), "l"(src_gl))
#define CP_COMMIT()  asm volatile("cp.async.commit_group;" ::: "memory")
#define CP_WAIT1()   asm volatile("cp.async.wait_group 1;" ::: "memory")

// f packed as bf16 k-pairs: g_fP[i2*64 + b] = {lo: f[b][2*i2], hi: f[b][2*i2+1]}
__device__ unsigned g_fP[(V / 2) * NB];   // 1 MB, L2-resident

__device__ __forceinline__ unsigned pack_bf16(float lo, float hi) {
    unsigned r;
    asm("cvt.rn.bf16x2.f32 %0, %1, %2;" : "=r"(r) : "f"(hi), "f"(lo));
    return r;
}

// ---------------------------------------------------------------------------
__global__ void prep_kernel(const float* __restrict__ func, float* __restrict__ out) {
    int idx = blockIdx.x * 256 + threadIdx.x;    // < (V/2)*NB = 262144
    int i2 = idx >> 6;
    int b  = idx & 63;
    float lo = func[b * STRIDE + 2 * i2];
    float hi = func[b * STRIDE + 2 * i2 + 1];
    g_fP[idx] = pack_bf16(lo, hi);
    if (idx < NB) {
        const float QI = 1000000000.0f;
        float a1 = func[idx * STRIDE + V];
        float a2 = func[idx * STRIDE + V + 1];
        out[idx * 3 + 0] = a1 * -QI;
        out[idx * 3 + 1] = (1.0f - (1.0f - a1) * (1.0f - a2)) * -QI;
        out[idx * 3 + 2] = 0.0f;
    }
}

// ---------------------------------------------------------------------------
// Persistent bf16 mma.sync GEMM, 128-thread CTAs, 4 CTAs/SM, 3-deep ring.
// ---------------------------------------------------------------------------
__global__ __launch_bounds__(128, 4)
void cooc_mma(const float* __restrict__ cooc,
              const float* __restrict__ arg,
              float* __restrict__ out) {
    extern __shared__ float sm[];
    float* Ds   = sm + DS_OFF;      // 32 x PD (one mt-slab at a time)
    float* sout = sm + SOUT_OFF;

    const int tid  = threadIdx.x;
    const int lane = tid & 31;
    const int wid  = tid >> 5;
    const int mg   = wid & 1;          // m-group: 32 m each (2 groups)
    const int kg   = wid >> 1;         // k-group: 16 k each (2 groups)
    const int quad = lane & 3;
    const int qid  = lane >> 2;
    const int bid  = blockIdx.x;

    const int nu    = 1 + (NUNITS - 1 - bid) / GRID;
    const int total = nu * SPU;

    unsigned smem_base;
    asm("{ .reg .u64 t; cvta.to.shared.u64 t, %1; cvt.u32.u64 %0, t; }"
        : "=r"(smem_base) : "l"(sm));

    // C: 32 rows x 64 floats = 512 x 16B chunks -> 4 per thread
    int crow[4], cc16[4];
    #pragma unroll
    for (int it = 0; it < 4; it++) {
        int flat = it * 128 + tid;
        crow[it] = flat >> 4;
        cc16[it] = flat & 15;
    }
    // f: 16 k2-rows x 64 words = 256 x 16B chunks -> 2 per thread
    int frow[2], fc16[2];
    #pragma unroll
    for (int it = 0; it < 2; it++) {
        int flat = it * 128 + tid;
        frow[it] = flat >> 4;
        fc16[it] = flat & 15;
    }

    const char* cooc_g = (const char*)__cvta_generic_to_global(cooc);
    const char* fP_g   = (const char*)__cvta_generic_to_global(g_fP);

    // -------- incremental issue-stream state ----
    int u_i  = bid;
    int sl_i = 0;
    int m0_i, k0_i;
    {
        int ks = u_i / NTILE;
        m0_i = (u_i - ks * NTILE) * MT;
        k0_i = ks * (V / KS);
    }
    int slot_i = 0;

    auto issue = [&]() {
        unsigned buf = smem_base + (unsigned)(slot_i * SB_BYTES);
        #pragma unroll
        for (int it = 0; it < 4; it++) {
            const char* src = cooc_g + ((size_t)(k0_i + crow[it]) * M3 + m0_i + cc16[it] * 4) * 4;
            CP16(buf + (unsigned)(crow[it] * PC + cc16[it] * 4) * 4, src);
        }
        unsigned fb = buf + CS_FLOATS * 4;
        #pragma unroll
        for (int it = 0; it < 2; it++) {
            const char* src = fP_g + ((size_t)((k0_i >> 1) + frow[it]) * 64 + fc16[it] * 4) * 4;
            CP16(fb + (unsigned)(frow[it] * PFW + fc16[it] * 4) * 4, src);
        }
    };
    auto adv = [&]() {
        slot_i = (slot_i == NST - 1) ? 0 : slot_i + 1;
        if (++sl_i == SPU) {
            sl_i = 0;
            u_i += GRID;
            if (u_i < NUNITS) {
                int ks = u_i / NTILE;
                m0_i = (u_i - ks * NTILE) * MT;
                k0_i = ks * (V / KS);
            }
        } else {
            k0_i += KC;
        }
    };

    float acc[2][8][4];
    #pragma unroll
    for (int mt = 0; mt < 2; mt++)
        #pragma unroll
        for (int nt = 0; nt < 8; nt++)
            #pragma unroll
            for (int r = 0; r < 4; r++) acc[mt][nt][r] = 0.0f;

    float po0 = 0.f, po1 = 0.f, po2 = 0.f;
    const int bb = tid & 63;
    const int mq = tid >> 6;     // 0..1
    const float* argb = arg + bb * STRIDE;

    int u_c  = bid;
    int m0_c;
    {
        int ks = u_c / NTILE;
        m0_c = (u_c - ks * NTILE) * MT;
    }

    issue(); CP_COMMIT(); adv();
    issue(); CP_COMMIT(); adv();

    int slot_c = 0;

    for (int g = 0; g < total; g++) {
        CP_WAIT1();
        __syncthreads();

        if (g + 2 < total) issue();
        CP_COMMIT();
        adv();

        // ---- compute stage g ----
        const float* buf = sm + slot_c * SB_FLOATS;
        slot_c = (slot_c == NST - 1) ? 0 : slot_c + 1;

        const float* ca = buf + (kg * 16 + 2 * quad) * PC + mg * 32 + qid;
        const unsigned* fb = (const unsigned*)(buf + CS_FLOATS) + (kg * 8 + quad) * PFW + qid;

        unsigned b0[8], b1[8];
        #pragma unroll
        for (int nt = 0; nt < 8; nt++) {
            b0[nt] = fb[nt * 8];
            b1[nt] = fb[4 * PFW + nt * 8];
        }

        #pragma unroll
        for (int mt = 0; mt < 2; mt++) {
            const float* cm = ca + mt * 16;
            unsigned a0 = pack_bf16(cm[0],          cm[PC]);
            unsigned a1 = pack_bf16(cm[8],          cm[PC + 8]);
            unsigned a2 = pack_bf16(cm[8 * PC],     cm[9 * PC]);
            unsigned a3 = pack_bf16(cm[8 * PC + 8], cm[9 * PC + 8]);
            #pragma unroll
            for (int nt = 0; nt < 8; nt++)
                MMA_BF16(acc[mt][nt], a0, a1, a2, a3, b0[nt], b1[nt]);
        }

        // ---- unit boundary: two-pass fold + reduce ----
        if ((g & (SPU - 1)) == SPU - 1) {
            #pragma unroll
            for (int p = 0; p < 2; p++) {
                __syncthreads();
                if (kg == 0) {
                    int cr = mg * 16 + qid;
                    #pragma unroll
                    for (int nt = 0; nt < 8; nt++) {
                        int bc = nt * 8 + 2 * quad;
                        Ds[cr * PD + bc]           = acc[p][nt][0];
                        Ds[cr * PD + bc + 1]       = acc[p][nt][1];
                        Ds[(cr + 8) * PD + bc]     = acc[p][nt][2];
                        Ds[(cr + 8) * PD + bc + 1] = acc[p][nt][3];
                    }
                }
                __syncthreads();
                if (kg == 1) {
                    int cr = mg * 16 + qid;
                    #pragma unroll
                    for (int nt = 0; nt < 8; nt++) {
                        int bc = nt * 8 + 2 * quad;
                        Ds[cr * PD + bc]           += acc[p][nt][0];
                        Ds[cr * PD + bc + 1]       += acc[p][nt][1];
                        Ds[(cr + 8) * PD + bc]     += acc[p][nt][2];
                        Ds[(cr + 8) * PD + bc + 1] += acc[p][nt][3];
                    }
                }
                __syncthreads();
                // reduce this slab: thread (bb, mq) over 16 rows
                // Ds row r=mq*16+mm -> m = m0 + mq*32 + p*16 + mm
                #pragma unroll 4
                for (int mm = 0; mm < 16; mm++) {
                    int m = m0_c + mq * 32 + p * 16 + mm;
                    unsigned j = (unsigned)m / 3u;
                    int k = m - 3 * (int)j;
                    float t = Ds[(mq * 16 + mm) * PD + bb] * __ldg(argb + j);
                    if (k == 0) po0 += t;
                    else if (k == 1) po1 += t;
                    else po2 += t;
                }
            }
            __syncthreads();

            #pragma unroll
            for (int mt = 0; mt < 2; mt++)
                #pragma unroll
                for (int nt = 0; nt < 8; nt++)
                    #pragma unroll
                    for (int r = 0; r < 4; r++) acc[mt][nt][r] = 0.0f;

            u_c += GRID;
            if (u_c < NUNITS) {
                int ks = u_c / NTILE;
                m0_c = (u_c - ks * NTILE) * MT;
            }
        }
    }

    // ---- final flush ----
    for (int t = tid; t < 192; t += 128) sout[t] = 0.0f;
    __syncthreads();
    atomicAdd(&sout[bb * 3 + 0], po0);
    atomicAdd(&sout[bb * 3 + 1], po1);
    atomicAdd(&sout[bb * 3 + 2], po2);
    __syncthreads();
    for (int t = tid; t < 192; t += 128) atomicAdd(&out[t], sout[t]);
}

// ---------------------------------------------------------------------------
extern "C" void kernel_launch(void* const* d_in, const int* in_sizes, int n_in,
                              void* d_out, int out_size) {
    const float* func = (const float*)d_in[0];
    const float* arg  = (const float*)d_in[1];
    const float* cooc = (const float*)d_in[2];
    float* out = (float*)d_out;

    cudaFuncSetAttribute(cooc_mma, cudaFuncAttributeMaxDynamicSharedMemorySize, SMEM_DYN);

    prep_kernel<<<((V / 2) * NB) / 256, 256>>>(func, out);
    cooc_mma<<<GRID, 128, SMEM_DYN>>>(cooc, arg, out);
}

// round 14
// speedup vs baseline: 1.1526x; 1.1163x over previous
#include <cuda_runtime.h>
#include <cstdint>

#define V 8192
#define NB 64
#define M3 24576
#define STRIDE 8194
#define MT 128
#define NTILE 192            // 24576 / 128 m-tiles
#define KS 16                // split-K factor -> 512 K per unit
#define NUNITS (NTILE * KS)  // 3072
#define GRID 296             // persistent, 2 CTAs/SM
#define KC 64                // k per stage (doubled)
#define SPU 8                // stages per unit (512/64)
#define NST 2                // double buffer

#define PC 132               // C tile pitch (floats): 2-row stride 264%32=8 -> conflict-free
#define PFW 72               // f pair-tile pitch (words)
#define PD 72

#define CS_FLOATS (KC * PC)                  // 8448
#define FS_WORDS  (32 * PFW)                 // 2304 (32 k2-rows)
#define SB_FLOATS (CS_FLOATS + FS_WORDS)     // 10752
#define SB_BYTES  (SB_FLOATS * 4)            // 43008
#define DS_OFF    (NST * SB_FLOATS)          // 21504
#define SOUT_OFF  (DS_OFF + 64 * PD)         // 26112
#define SMEM_DYN  ((SOUT_OFF + 192) * 4)     // 105216 B -> 2 CTAs/SM

#define MMA_BF16(d, a0, a1, a2, a3, b0, b1)                                   \
    asm volatile("mma.sync.aligned.m16n8k16.row.col.f32.bf16.bf16.f32 "       \
        "{%0,%1,%2,%3}, {%4,%5,%6,%7}, {%8,%9}, {%0,%1,%2,%3};"               \
        : "+f"((d)[0]), "+f"((d)[1]), "+f"((d)[2]), "+f"((d)[3])              \
        : "r"(a0), "r"(a1), "r"(a2), "r"(a3), "r"(b0), "r"(b1))

#define CP16(dst_u32, src_gl) \
    asm volatile("cp.async.cg.shared.global [%0], [%1], 16;" :: "r"(dst_u32), "l"(src_gl))
#define CP_COMMIT()  asm volatile("cp.async.commit_group;" ::: "memory")
#define CP_WAIT1()   asm volatile("cp.async.wait_group 1;" ::: "memory")

// f packed as bf16 k-pairs: g_fP[i2*64 + b] = {lo: f[b][2*i2], hi: f[b][2*i2+1]}
__device__ unsigned g_fP[(V / 2) * NB];   // 1 MB, L2-resident

__device__ __forceinline__ unsigned pack_bf16(float lo, float hi) {
    unsigned r;
    asm("cvt.rn.bf16x2.f32 %0, %1, %2;" : "=r"(r) : "f"(hi), "f"(lo));
    return r;
}

// ---------------------------------------------------------------------------
__global__ void prep_kernel(const float* __restrict__ func, float* __restrict__ out) {
    int idx = blockIdx.x * 256 + threadIdx.x;    // < (V/2)*NB = 262144
    int i2 = idx >> 6;
    int b  = idx & 63;
    float lo = func[b * STRIDE + 2 * i2];
    float hi = func[b * STRIDE + 2 * i2 + 1];
    g_fP[idx] = pack_bf16(lo, hi);
    if (idx < NB) {
        const float QI = 1000000000.0f;
        float a1 = func[idx * STRIDE + V];
        float a2 = func[idx * STRIDE + V + 1];
        out[idx * 3 + 0] = a1 * -QI;
        out[idx * 3 + 1] = (1.0f - (1.0f - a1) * (1.0f - a2)) * -QI;
        out[idx * 3 + 2] = 0.0f;
    }
}

// ---------------------------------------------------------------------------
// Persistent bf16 mma.sync GEMM, 2 CTAs/SM, KC=64 double-buffered stages.
// ---------------------------------------------------------------------------
__global__ __launch_bounds__(256, 2)
void cooc_mma(const float* __restrict__ cooc,
              const float* __restrict__ arg,
              float* __restrict__ out) {
    extern __shared__ float sm[];
    float* Ds   = sm + DS_OFF;
    float* sout = sm + SOUT_OFF;

    const int tid  = threadIdx.x;
    const int lane = tid & 31;
    const int wid  = tid >> 5;
    const int mg   = wid & 3;          // m-group: 32 m each
    const int kg   = wid >> 2;         // k-group: 32 k each within stage
    const int quad = lane & 3;
    const int qid  = lane >> 2;
    const int bid  = blockIdx.x;

    const int nu    = 1 + (NUNITS - 1 - bid) / GRID;
    const int total = nu * SPU;

    unsigned smem_base;
    asm("{ .reg .u64 t; cvta.to.shared.u64 t, %1; cvt.u32.u64 %0, t; }"
        : "=r"(smem_base) : "l"(sm));

    // C: 64 rows x 128 floats = 2048 x 16B chunks -> 8 per thread
    int crow[8], cc16[8];
    #pragma unroll
    for (int it = 0; it < 8; it++) {
        int flat = it * 256 + tid;
        crow[it] = flat >> 5;
        cc16[it] = flat & 31;
    }
    // f: 32 k2-rows x 64 words = 512 x 16B chunks -> 2 per thread
    int frow[2], fc16[2];
    #pragma unroll
    for (int it = 0; it < 2; it++) {
        int flat = it * 256 + tid;
        frow[it] = flat >> 4;
        fc16[it] = flat & 15;
    }

    const char* cooc_g = (const char*)__cvta_generic_to_global(cooc);
    const char* fP_g   = (const char*)__cvta_generic_to_global(g_fP);

    // -------- incremental issue-stream state ----
    int u_i  = bid;
    int sl_i = 0;
    int m0_i, k0_i;
    {
        int ks = u_i / NTILE;
        m0_i = (u_i - ks * NTILE) * MT;
        k0_i = ks * (V / KS);
    }
    int slot_i = 0;

    auto issue = [&]() {
        unsigned buf = smem_base + (unsigned)(slot_i * SB_BYTES);
        #pragma unroll
        for (int it = 0; it < 8; it++) {
            const char* src = cooc_g + ((size_t)(k0_i + crow[it]) * M3 + m0_i + cc16[it] * 4) * 4;
            CP16(buf + (unsigned)(crow[it] * PC + cc16[it] * 4) * 4, src);
        }
        unsigned fb = buf + CS_FLOATS * 4;
        #pragma unroll
        for (int it = 0; it < 2; it++) {
            const char* src = fP_g + ((size_t)((k0_i >> 1) + frow[it]) * 64 + fc16[it] * 4) * 4;
            CP16(fb + (unsigned)(frow[it] * PFW + fc16[it] * 4) * 4, src);
        }
    };
    auto adv = [&]() {
        slot_i ^= 1;
        if (++sl_i == SPU) {
            sl_i = 0;
            u_i += GRID;
            if (u_i < NUNITS) {
                int ks = u_i / NTILE;
                m0_i = (u_i - ks * NTILE) * MT;
                k0_i = ks * (V / KS);
            }
        } else {
            k0_i += KC;
        }
    };

    float acc[2][8][4];
    #pragma unroll
    for (int mt = 0; mt < 2; mt++)
        #pragma unroll
        for (int nt = 0; nt < 8; nt++)
            #pragma unroll
            for (int r = 0; r < 4; r++) acc[mt][nt][r] = 0.0f;

    float po0 = 0.f, po1 = 0.f, po2 = 0.f;
    const int bb = tid & 63;
    const int mq = tid >> 6;
    const float* argb = arg + bb * STRIDE;

    int u_c  = bid;
    int m0_c;
    {
        int ks = u_c / NTILE;
        m0_c = (u_c - ks * NTILE) * MT;
    }

    issue(); CP_COMMIT(); adv();
    issue(); CP_COMMIT(); adv();

    for (int g = 0; g < total; g++) {
        CP_WAIT1();                        // stage g arrived (g+1 pending)
        __syncthreads();

        // ---- compute stage g from slot g&1 ----
        const float* buf = sm + (g & 1) * SB_FLOATS;

        #pragma unroll
        for (int kk = 0; kk < 2; kk++) {
            const float* ca = buf + (kg * 32 + kk * 16 + 2 * quad) * PC + mg * 32 + qid;
            const unsigned* fb = (const unsigned*)(buf + CS_FLOATS)
                               + (kg * 16 + kk * 8 + quad) * PFW + qid;

            unsigned b0[8], b1[8];
            #pragma unroll
            for (int nt = 0; nt < 8; nt++) {
                b0[nt] = fb[nt * 8];
                b1[nt] = fb[4 * PFW + nt * 8];
            }

            #pragma unroll
            for (int mt = 0; mt < 2; mt++) {
                const float* cm = ca + mt * 16;
                unsigned a0 = pack_bf16(cm[0],          cm[PC]);
                unsigned a1 = pack_bf16(cm[8],          cm[PC + 8]);
                unsigned a2 = pack_bf16(cm[8 * PC],     cm[9 * PC]);
                unsigned a3 = pack_bf16(cm[8 * PC + 8], cm[9 * PC + 8]);
                #pragma unroll
                for (int nt = 0; nt < 8; nt++)
                    MMA_BF16(acc[mt][nt], a0, a1, a2, a3, b0[nt], b1[nt]);
            }
        }

        // ---- unit boundary: two-pass fold + reduce (starts with sync) ----
        if ((g & (SPU - 1)) == SPU - 1) {
            #pragma unroll
            for (int p = 0; p < 2; p++) {
                __syncthreads();
                if (kg == 0) {
                    int cr = mg * 16 + qid;
                    #pragma unroll
                    for (int nt = 0; nt < 8; nt++) {
                        int bc = nt * 8 + 2 * quad;
                        Ds[cr * PD + bc]           = acc[p][nt][0];
                        Ds[cr * PD + bc + 1]       = acc[p][nt][1];
                        Ds[(cr + 8) * PD + bc]     = acc[p][nt][2];
                        Ds[(cr + 8) * PD + bc + 1] = acc[p][nt][3];
                    }
                }
                __syncthreads();
                if (kg == 1) {
                    int cr = mg * 16 + qid;
                    #pragma unroll
                    for (int nt = 0; nt < 8; nt++) {
                        int bc = nt * 8 + 2 * quad;
                        Ds[cr * PD + bc]           += acc[p][nt][0];
                        Ds[cr * PD + bc + 1]       += acc[p][nt][1];
                        Ds[(cr + 8) * PD + bc]     += acc[p][nt][2];
                        Ds[(cr + 8) * PD + bc + 1] += acc[p][nt][3];
                    }
                }
                __syncthreads();
                #pragma unroll 4
                for (int mm = 0; mm < 16; mm++) {
                    int m = m0_c + mq * 32 + p * 16 + mm;
                    unsigned j = (unsigned)m / 3u;
                    int k = m - 3 * (int)j;
                    float t = Ds[(mq * 16 + mm) * PD + bb] * __ldg(argb + j);
                    if (k == 0) po0 += t;
                    else if (k == 1) po1 += t;
                    else po2 += t;
                }
            }
            __syncthreads();

            #pragma unroll
            for (int mt = 0; mt < 2; mt++)
                #pragma unroll
                for (int nt = 0; nt < 8; nt++)
                    #pragma unroll
                    for (int r = 0; r < 4; r++) acc[mt][nt][r] = 0.0f;

            u_c += GRID;
            if (u_c < NUNITS) {
                int ks = u_c / NTILE;
                m0_c = (u_c - ks * NTILE) * MT;
            }
        } else {
            __syncthreads();               // all warps done reading slot g&1
        }

        // refill the slot we just finished with stage g+2
        if (g + 2 < total) issue();
        CP_COMMIT();
        adv();
    }

    // ---- final flush ----
    if (tid < 192) sout[tid] = 0.0f;
    __syncthreads();
    atomicAdd(&sout[bb * 3 + 0], po0);
    atomicAdd(&sout[bb * 3 + 1], po1);
    atomicAdd(&sout[bb * 3 + 2], po2);
    __syncthreads();
    if (tid < 192) atomicAdd(&out[tid], sout[tid]);
}

// ---------------------------------------------------------------------------
extern "C" void kernel_launch(void* const* d_in, const int* in_sizes, int n_in,
                              void* d_out, int out_size) {
    const float* func = (const float*)d_in[0];
    const float* arg  = (const float*)d_in[1];
    const float* cooc = (const float*)d_in[2];
    float* out = (float*)d_out;

    cudaFuncSetAttribute(cooc_mma, cudaFuncAttributeMaxDynamicSharedMemorySize, SMEM_DYN);

    prep_kernel<<<((V / 2) * NB) / 256, 256>>>(func, out);
    cooc_mma<<<GRID, 256, SMEM_DYN>>>(cooc, arg, out);
}

// round 15
// speedup vs baseline: 1.3523x; 1.1733x over previous
#include <cuda_runtime.h>
#include <cstdint>

#define V 8192
#define NB 64
#define M3 24576
#define STRIDE 8194
#define MT 128
#define NTILE 192            // 24576 / 128 m-tiles
#define KS 16                // split-K factor -> 512 K per unit
#define NUNITS (NTILE * KS)  // 3072
#define GRID 444             // persistent, 3 CTAs/SM
#define KC 32
#define SPU 16               // stages per unit (512/32)
#define NST 3                // cp.async ring depth

#define PC 132               // C tile pitch (floats): 2-row stride 264%32=8 -> conflict-free
#define PFW 72               // f pair-tile pitch (words)
#define PD 72

#define CS_FLOATS (KC * PC)                  // 4224
#define FS_WORDS  (16 * PFW)                 // 1152
#define SB_FLOATS (CS_FLOATS + FS_WORDS)     // 5376
#define SB_BYTES  (SB_FLOATS * 4)            // 21504
#define DS_OFF    (NST * SB_FLOATS)          // 16128 floats
#define SOUT_OFF  (DS_OFF + 32 * PD)         // 18432
#define SMEM_DYN  ((SOUT_OFF + 192) * 4)     // 74496 B -> 3 CTAs/SM

#define MMA_BF16(d, a0, a1, a2, a3, b0, b1)                                   \
    asm volatile("mma.sync.aligned.m16n8k16.row.col.f32.bf16.bf16.f32 "       \
        "{%0,%1,%2,%3}, {%4,%5,%6,%7}, {%8,%9}, {%0,%1,%2,%3};"               \
        : "+f"((d)[0]), "+f"((d)[1]), "+f"((d)[2]), "+f"((d)[3])              \
        : "r"(a0), "r"(a1), "r"(a2), "r"(a3), "r"(b0), "r"(b1))

#define CP16(dst_u32, src_gl) \
    asm volatile("cp.async.cg.shared.global [%0], [%1], 16;" :: "r"(dst_u32), "l"(src_gl))
#define CP_COMMIT()  asm volatile("cp.async.commit_group;" ::: "memory")
#define CP_WAIT1()   asm volatile("cp.async.wait_group 1;" ::: "memory")

// f packed as bf16 k-pairs: g_fP[i2*64 + b] = {lo: f[b][2*i2], hi: f[b][2*i2+1]}
__device__ unsigned g_fP[(V / 2) * NB];   // 1 MB, L2-resident

__device__ __forceinline__ unsigned pack_bf16(float lo, float hi) {
    unsigned r;
    asm("cvt.rn.bf16x2.f32 %0, %1, %2;" : "=r"(r) : "f"(hi), "f"(lo));
    return r;
}

// ---------------------------------------------------------------------------
__global__ void prep_kernel(const float* __restrict__ func, float* __restrict__ out) {
    int idx = blockIdx.x * 256 + threadIdx.x;    // < (V/2)*NB = 262144
    int i2 = idx >> 6;
    int b  = idx & 63;
    float lo = func[b * STRIDE + 2 * i2];
    float hi = func[b * STRIDE + 2 * i2 + 1];
    g_fP[idx] = pack_bf16(lo, hi);
    if (idx < NB) {
        const float QI = 1000000000.0f;
        float a1 = func[idx * STRIDE + V];
        float a2 = func[idx * STRIDE + V + 1];
        out[idx * 3 + 0] = a1 * -QI;
        out[idx * 3 + 1] = (1.0f - (1.0f - a1) * (1.0f - a2)) * -QI;
        out[idx * 3 + 2] = 0.0f;
    }
}

// ---------------------------------------------------------------------------
// Persistent bf16 mma.sync GEMM, 3 CTAs/SM (32-reg accumulators, mg x bg split).
// ---------------------------------------------------------------------------
__global__ __launch_bounds__(256, 3)
void cooc_mma(const float* __restrict__ cooc,
              const float* __restrict__ arg,
              float* __restrict__ out) {
    extern __shared__ float sm[];
    float* Ds   = sm + DS_OFF;      // 32 rows x PD (one mg-slab per pass)
    float* sout = sm + SOUT_OFF;

    const int tid  = threadIdx.x;
    const int lane = tid & 31;
    const int wid  = tid >> 5;
    const int mg   = wid & 3;          // m-group: 32 m each
    const int bg   = wid >> 2;         // b-group: 32 b each
    const int quad = lane & 3;
    const int qid  = lane >> 2;
    const int bid  = blockIdx.x;

    const int nu    = 1 + (NUNITS - 1 - bid) / GRID;
    const int total = nu * SPU;

    unsigned smem_base;
    asm("{ .reg .u64 t; cvta.to.shared.u64 t, %1; cvt.u32.u64 %0, t; }"
        : "=r"(smem_base) : "l"(sm));

    const char* cooc_g = (const char*)__cvta_generic_to_global(cooc);
    const char* fP_g   = (const char*)__cvta_generic_to_global(g_fP);

    // -------- incremental issue-stream state ----
    int u_i  = bid;
    int sl_i = 0;
    int m0_i, k0_i;
    {
        int ks = u_i / NTILE;
        m0_i = (u_i - ks * NTILE) * MT;
        k0_i = ks * (V / KS);
    }
    int slot_i = 0;

    auto issue = [&]() {
        unsigned buf = smem_base + (unsigned)(slot_i * SB_BYTES);
        #pragma unroll
        for (int it = 0; it < 4; it++) {
            int flat = it * 256 + tid;
            int row = flat >> 5, c16 = flat & 31;
            const char* src = cooc_g + ((size_t)(k0_i + row) * M3 + m0_i + c16 * 4) * 4;
            CP16(buf + (unsigned)(row * PC + c16 * 4) * 4, src);
        }
        unsigned fbs = buf + CS_FLOATS * 4;
        {
            int row = tid >> 4, c16 = tid & 15;
            const char* src = fP_g + ((size_t)((k0_i >> 1) + row) * 64 + c16 * 4) * 4;
            CP16(fbs + (unsigned)(row * PFW + c16 * 4) * 4, src);
        }
    };
    auto adv = [&]() {
        slot_i = (slot_i == NST - 1) ? 0 : slot_i + 1;
        if (++sl_i == SPU) {
            sl_i = 0;
            u_i += GRID;
            if (u_i < NUNITS) {
                int ks = u_i / NTILE;
                m0_i = (u_i - ks * NTILE) * MT;
                k0_i = ks * (V / KS);
            }
        } else {
            k0_i += KC;
        }
    };

    float acc[2][4][4];
    #pragma unroll
    for (int mt = 0; mt < 2; mt++)
        #pragma unroll
        for (int nt = 0; nt < 4; nt++)
            #pragma unroll
            for (int r = 0; r < 4; r++) acc[mt][nt][r] = 0.0f;

    float po0 = 0.f, po1 = 0.f, po2 = 0.f;
    const int bb = tid & 63;
    const int mq = tid >> 6;     // 0..3
    const float* argb = arg + bb * STRIDE;

    int u_c  = bid;
    int m0_c;
    {
        int ks = u_c / NTILE;
        m0_c = (u_c - ks * NTILE) * MT;
    }

    issue(); CP_COMMIT(); adv();
    issue(); CP_COMMIT(); adv();

    int slot_c = 0;

    for (int g = 0; g < total; g++) {
        CP_WAIT1();
        __syncthreads();

        if (g + 2 < total) issue();
        CP_COMMIT();
        adv();

        // ---- compute stage g: full 32-k, warp tile 32m x 32b ----
        const float* buf = sm + slot_c * SB_FLOATS;
        slot_c = (slot_c == NST - 1) ? 0 : slot_c + 1;

        #pragma unroll
        for (int kk = 0; kk < 2; kk++) {
            const float* ca = buf + (kk * 16 + 2 * quad) * PC + mg * 32 + qid;
            const unsigned* fb = (const unsigned*)(buf + CS_FLOATS)
                               + (kk * 8 + quad) * PFW + bg * 32 + qid;

            unsigned b0[4], b1[4];
            #pragma unroll
            for (int nt = 0; nt < 4; nt++) {
                b0[nt] = fb[nt * 8];
                b1[nt] = fb[4 * PFW + nt * 8];
            }

            #pragma unroll
            for (int mt = 0; mt < 2; mt++) {
                const float* cm = ca + mt * 16;
                unsigned a0 = pack_bf16(cm[0],          cm[PC]);
                unsigned a1 = pack_bf16(cm[8],          cm[PC + 8]);
                unsigned a2 = pack_bf16(cm[8 * PC],     cm[9 * PC]);
                unsigned a3 = pack_bf16(cm[8 * PC + 8], cm[9 * PC + 8]);
                #pragma unroll
                for (int nt = 0; nt < 4; nt++)
                    MMA_BF16(acc[mt][nt], a0, a1, a2, a3, b0[nt], b1[nt]);
            }
        }

        // ---- unit boundary: 4 write-only passes (no kg fold needed) ----
        if ((g & (SPU - 1)) == SPU - 1) {
            #pragma unroll
            for (int p = 0; p < 4; p++) {
                __syncthreads();
                if (mg == p) {
                    #pragma unroll
                    for (int mt = 0; mt < 2; mt++) {
                        int cr = mt * 16 + qid;
                        #pragma unroll
                        for (int nt = 0; nt < 4; nt++) {
                            int bc = bg * 32 + nt * 8 + 2 * quad;
                            Ds[cr * PD + bc]           = acc[mt][nt][0];
                            Ds[cr * PD + bc + 1]       = acc[mt][nt][1];
                            Ds[(cr + 8) * PD + bc]     = acc[mt][nt][2];
                            Ds[(cr + 8) * PD + bc + 1] = acc[mt][nt][3];
                        }
                    }
                }
                __syncthreads();
                // reduce this 32-row slab: thread (bb, mq) over 8 rows
                #pragma unroll 4
                for (int mm = 0; mm < 8; mm++) {
                    int m = m0_c + p * 32 + mq * 8 + mm;
                    unsigned j = (unsigned)m / 3u;
                    int k = m - 3 * (int)j;
                    float t = Ds[(mq * 8 + mm) * PD + bb] * __ldg(argb + j);
                    if (k == 0) po0 += t;
                    else if (k == 1) po1 += t;
                    else po2 += t;
                }
            }
            __syncthreads();

            #pragma unroll
            for (int mt = 0; mt < 2; mt++)
                #pragma unroll
                for (int nt = 0; nt < 4; nt++)
                    #pragma unroll
                    for (int r = 0; r < 4; r++) acc[mt][nt][r] = 0.0f;

            u_c += GRID;
            if (u_c < NUNITS) {
                int ks = u_c / NTILE;
                m0_c = (u_c - ks * NTILE) * MT;
            }
        }
    }

    // ---- final flush ----
    if (tid < 192) sout[tid] = 0.0f;
    __syncthreads();
    atomicAdd(&sout[bb * 3 + 0], po0);
    atomicAdd(&sout[bb * 3 + 1], po1);
    atomicAdd(&sout[bb * 3 + 2], po2);
    __syncthreads();
    if (tid < 192) atomicAdd(&out[tid], sout[tid]);
}

// ---------------------------------------------------------------------------
extern "C" void kernel_launch(void* const* d_in, const int* in_sizes, int n_in,
                              void* d_out, int out_size) {
    const float* func = (const float*)d_in[0];
    const float* arg  = (const float*)d_in[1];
    const float* cooc = (const float*)d_in[2];
    float* out = (float*)d_out;

    cudaFuncSetAttribute(cooc_mma, cudaFuncAttributeMaxDynamicSharedMemorySize, SMEM_DYN);

    prep_kernel<<<((V / 2) * NB) / 256, 256>>>(func, out);
    cooc_mma<<<GRID, 256, SMEM_DYN>>>(cooc, arg, out);
}